// round 4
// baseline (speedup 1.0000x reference)
#include <cuda_runtime.h>
#include <cuda_fp16.h>

#define HH 200
#define WW 320
#define CC 256
#define HWSZ (HH * WW)
#define RS 14
#define BINS (RS * RS)

// Scratch: transposed feature [H][W][C] fp16 (32.8 MB), per-pixel channel max
// M[h][w] (ordered-uint), per-bin best-bound sample (packed), per-bin maxima.
__device__ __align__(128) static __half g_featT[(size_t)HWSZ * CC];
__device__ static unsigned g_M[HWSZ];
__device__ static unsigned long long g_best[BINS];
__device__ static unsigned g_bins[BINS];

// Monotonic float <-> uint encoding so atomicMax on unsigned == float max
__device__ __forceinline__ unsigned enc_f(float f) {
    unsigned u = __float_as_uint(f);
    return (u & 0x80000000u) ? ~u : (u | 0x80000000u);
}
__device__ __forceinline__ float dec_f(unsigned u) {
    return __uint_as_float((u & 0x80000000u) ? (u ^ 0x80000000u) : ~u);
}

__global__ void init_kernel() {
    int t = blockIdx.x * blockDim.x + threadIdx.x;
    if (t < HWSZ) g_M[t] = 0u;
    if (blockIdx.x == 0 && threadIdx.x < BINS) {
        g_best[threadIdx.x] = 0ull;
        g_bins[threadIdx.x] = 0u;
    }
}

// Transpose feature [C][H*W] fp32 -> g_featT [H*W][C] fp16, AND accumulate the
// per-pixel max over the fp16-ROUNDED channel values into g_M (sound bound).
__global__ void transpose_kernel(const float* __restrict__ A) {
    __shared__ float tile[64][33];
    int hw0 = blockIdx.x * 32;
    int c0 = blockIdx.y * 64;
    int tx = threadIdx.x, ty = threadIdx.y;  // 32 x 8
#pragma unroll
    for (int j = 0; j < 64; j += 8)
        tile[ty + j][tx] = A[(size_t)(c0 + ty + j) * HWSZ + hw0 + tx];
    __syncthreads();
    // warp ty handles hw rows ty+8*rr; lane tx = channel pair (2tx, 2tx+1)
#pragma unroll
    for (int rr = 0; rr < 4; rr++) {
        int hwr = ty + rr * 8;
        __half2 h = __floats2half2_rn(tile[2 * tx][hwr], tile[2 * tx + 1][hwr]);
        ((__half2*)(g_featT + (size_t)(hw0 + hwr) * CC + c0))[tx] = h;
        float2 f = __half22float2(h);
        float v = fmaxf(f.x, f.y);
#pragma unroll
        for (int o = 16; o; o >>= 1)
            v = fmaxf(v, __shfl_xor_sync(0xffffffffu, v, o));
        if (tx == 0) atomicMax(&g_M[hw0 + hwr], enc_f(v));
    }
}

// Convex-interp upper bound on max_c bilinear_c at (y, x). Valid because all
// samples are interior (weights in [0,1], sum 1). +1e-3 margin absorbs fp
// ordering differences between bound and exact paths.
__device__ __forceinline__ float sample_bound(float y, float x) {
    int yf = (int)floorf(y), xf = (int)floorf(x);
    int y1 = min(max(yf, 0), HH - 1);
    int y2 = min(max(yf + 1, 0), HH - 1);
    int x1 = min(max(xf, 0), WW - 1);
    int x2 = min(max(xf + 1, 0), WW - 1);
    float wxl = x - (float)x1, wxh = (float)x2 - x;
    float wyl = y - (float)y1, wyh = (float)y2 - y;
    float m11 = dec_f(g_M[y1 * WW + x1]);
    float m12 = dec_f(g_M[y1 * WW + x2]);
    float m21 = dec_f(g_M[y2 * WW + x1]);
    float m22 = dec_f(g_M[y2 * WW + x2]);
    return (m11 * wxh + m12 * wxl) * wyh + (m21 * wxh + m22 * wxl) * wyl + 1e-3f;
}

// Exact per-lane partial: lane covers 8 channels (uint4 of fp16). Warp covers
// all 256 channels; caller warp-reduces.
__device__ __forceinline__ float sample_exact_lane(float y, float x, int lane) {
    int yf = (int)floorf(y), xf = (int)floorf(x);
    int y1 = min(max(yf, 0), HH - 1);
    int y2 = min(max(yf + 1, 0), HH - 1);
    int x1 = min(max(xf, 0), WW - 1);
    int x2 = min(max(xf + 1, 0), WW - 1);
    float wxl = x - (float)x1, wxh = (float)x2 - x;
    float wyl = y - (float)y1, wyh = (float)y2 - y;
    const uint4* p11 = (const uint4*)(g_featT + (size_t)(y1 * WW + x1) * CC);
    const uint4* p12 = (const uint4*)(g_featT + (size_t)(y1 * WW + x2) * CC);
    const uint4* p21 = (const uint4*)(g_featT + (size_t)(y2 * WW + x1) * CC);
    const uint4* p22 = (const uint4*)(g_featT + (size_t)(y2 * WW + x2) * CC);
    uint4 A = p11[lane];
    uint4 B = p12[lane];
    uint4 C = p21[lane];
    uint4 D = p22[lane];
    float vmax = __int_as_float(0xff800000);
#pragma unroll
    for (int k = 0; k < 4; k++) {
        float2 fa = __half22float2(*(const __half2*)(&((const unsigned*)&A)[k]));
        float2 fb = __half22float2(*(const __half2*)(&((const unsigned*)&B)[k]));
        float2 fc = __half22float2(*(const __half2*)(&((const unsigned*)&C)[k]));
        float2 fd = __half22float2(*(const __half2*)(&((const unsigned*)&D)[k]));
        float v0 = (fa.x * wxh + fb.x * wxl) * wyh + (fc.x * wxh + fd.x * wxl) * wyl;
        float v1 = (fa.y * wxh + fb.y * wxl) * wyh + (fc.y * wxh + fd.y * wxl) * wyl;
        vmax = fmaxf(vmax, fmaxf(v0, v1));
    }
    return vmax;
}

// Recover sample coords from linear sample id s = r*784 + mn*4 + pt.
__device__ __forceinline__ void sample_coords(const float* __restrict__ rois,
                                              int s, int* mn_out,
                                              float* y_out, float* x_out) {
    int r = s / (BINS * 4);
    int q = s - r * (BINS * 4);
    int mn = q >> 2;
    int pt = q & 3;
    int m = mn / RS;
    int n = mn - m * RS;
    float r0 = __ldg(rois + 4 * r + 0);
    float r1 = __ldg(rois + 4 * r + 1);
    float r2 = __ldg(rois + 4 * r + 2);
    float r3 = __ldg(rois + 4 * r + 3);
    float sh = (r2 - r0) / (float)RS;
    float sw = (r3 - r1) / (float)RS;
    float fy = (pt >> 1) ? (2.0f / 3.0f) : (1.0f / 3.0f);
    float fx = (pt & 1) ? (2.0f / 3.0f) : (1.0f / 3.0f);
    *mn_out = mn;
    *y_out = (r0 + sh * (float)m) + sh * fy;
    *x_out = (r1 + sw * (float)n) + sw * fx;
}

// Phase A: per-sample upper bound; per-bin argmax(bound) via packed u64 atomic.
__global__ void bounds_kernel(const float* __restrict__ rois, int total) {
    int s = blockIdx.x * blockDim.x + threadIdx.x;
    unsigned long long packed = 0ull;
    int mn = 0;
    if (s < total) {
        float y, x;
        sample_coords(rois, s, &mn, &y, &x);
        float U = sample_bound(y, x);
        packed = ((unsigned long long)enc_f(U) << 32) | (unsigned)s;
    }
    // reduce over the 4 sample points of a bin (pt lives in the low 2 bits of
    // s, and roi boundaries are multiples of 4, so 4-lane groups are aligned)
    unsigned long long o1 = __shfl_down_sync(0xffffffffu, packed, 1, 4);
    packed = packed > o1 ? packed : o1;
    unsigned long long o2 = __shfl_down_sync(0xffffffffu, packed, 2, 4);
    packed = packed > o2 ? packed : o2;
    if (s < total && (s & 3) == 0) atomicMax(&g_best[mn], packed);
}

// Phase B: per bin, exactly evaluate the best-bound sample -> lower bound L.
__global__ void seed_kernel(const float* __restrict__ rois) {
    int w = (blockIdx.x * blockDim.x + threadIdx.x) >> 5;
    int lane = threadIdx.x & 31;
    if (w >= BINS) return;
    int s = (unsigned)(g_best[w] & 0xffffffffull);
    int mn;
    float y, x;
    sample_coords(rois, s, &mn, &y, &x);
    float v = sample_exact_lane(y, x, lane);
#pragma unroll
    for (int o = 16; o; o >>= 1)
        v = fmaxf(v, __shfl_xor_sync(0xffffffffu, v, o));
    if (lane == 0) atomicMax(&g_bins[w], enc_f(v));
}

// Phase C: warp per (roi, bin); prune sample points whose bound <= current L.
__global__ void prune_exact_kernel(const float* __restrict__ rois, int R) {
    int warp = threadIdx.x >> 5;
    int lane = threadIdx.x & 31;
    int wid = blockIdx.x * (blockDim.x >> 5) + warp;
    if (wid >= R * BINS) return;
    int r = wid / BINS;
    int mn = wid - r * BINS;
    int m = mn / RS;
    int n = mn - m * RS;

    float r0 = __ldg(rois + 4 * r + 0);
    float r1 = __ldg(rois + 4 * r + 1);
    float r2 = __ldg(rois + 4 * r + 2);
    float r3 = __ldg(rois + 4 * r + 3);
    float sh = (r2 - r0) / (float)RS;
    float sw = (r3 - r1) / (float)RS;
    float yb = r0 + sh * (float)m;
    float xb = r1 + sw * (float)n;
    float ys[2] = {yb + sh * (1.0f / 3.0f), yb + sh * (2.0f / 3.0f)};
    float xs[2] = {xb + sw * (1.0f / 3.0f), xb + sw * (2.0f / 3.0f)};

    float vmax = __int_as_float(0xff800000);
    bool any = false;
#pragma unroll
    for (int pt = 0; pt < 4; pt++) {
        float y = ys[pt >> 1], x = xs[pt & 1];
        float L = dec_f(__ldcg(&g_bins[mn]));  // L2-fresh for better pruning
        float U = sample_bound(y, x);
        if (U > L) {
            vmax = fmaxf(vmax, sample_exact_lane(y, x, lane));
            any = true;
        }
    }
    if (__any_sync(0xffffffffu, any)) {
#pragma unroll
        for (int o = 16; o; o >>= 1)
            vmax = fmaxf(vmax, __shfl_xor_sync(0xffffffffu, vmax, o));
        if (lane == 0) atomicMax(&g_bins[mn], enc_f(vmax));
    }
}

// Broadcast: gridDim*blockDim chosen == 0 (mod 49) in float4 units, so each
// thread's bin value is CONSTANT across iterations: one smem read, pure stores.
__global__ void bcast_kernel(float* __restrict__ out, int total4) {
    __shared__ float4 s4[49];
    int t = threadIdx.x;
    if (t < BINS) ((float*)s4)[t] = dec_f(g_bins[t]);
    __syncthreads();
    int g0 = blockIdx.x * blockDim.x + t;
    float4 v = s4[g0 % 49];
    int stride = blockDim.x * gridDim.x;  // 931*256 = 49*4864
#pragma unroll 7
    for (int g = g0; g < total4; g += stride)
        ((float4*)out)[g] = v;
}

extern "C" void kernel_launch(void* const* d_in, const int* in_sizes, int n_in,
                              void* d_out, int out_size) {
    const float* feature = (const float*)d_in[0];
    const float* rois = (const float*)d_in[1];
    int R = in_sizes[1] / 4;

    init_kernel<<<(HWSZ + 255) / 256, 256>>>();

    dim3 tb(32, 8);
    dim3 tg(HWSZ / 32, CC / 64);
    transpose_kernel<<<tg, tb>>>(feature);

    int total = R * BINS * 4;
    bounds_kernel<<<(total + 255) / 256, 256>>>(rois, total);

    seed_kernel<<<(BINS * 32 + 255) / 256, 256>>>(rois);

    int warps = R * BINS;
    prune_exact_kernel<<<(warps + 7) / 8, 256>>>(rois, R);

    int total4 = out_size / 4;
    bcast_kernel<<<931, 256>>>((float*)d_out, total4);
}